// round 1
// baseline (speedup 1.0000x reference)
#include <cuda_runtime.h>
#include <cuda_bf16.h>
#include <math.h>

// ---------------- scratch (device globals: no allocation allowed) ----------
__device__ float g_q[2048 * 4096];
__device__ float g_k[2048 * 1024];
__device__ float g_v[2048 * 1024];
__device__ float g_attn[2048 * 4096];
__device__ float g_cos[2048 * 64];
__device__ float g_sin[2048 * 64];

// ---------------- tiled fp32 SGEMM: C[M,N] = A[M,K] @ B[K,N] ---------------
// BM=BN=128, BK=16, 256 threads, 8x8 per thread. M,N,K multiples of tile dims.
__global__ __launch_bounds__(256) void sgemm128(const float* __restrict__ A,
                                                const float* __restrict__ B,
                                                float* __restrict__ C,
                                                int M, int N, int K) {
    __shared__ float As[16][128];
    __shared__ float Bs[16][128];

    const int bx = blockIdx.x;   // N tile
    const int by = blockIdx.y;   // M tile
    const int tid = threadIdx.x;
    const int tcol = tid & 15;   // 0..15
    const int trow = tid >> 4;   // 0..15

    const float* Ab = A + (size_t)by * 128 * K;
    const float* Bb = B + (size_t)bx * 128;

    const int aRow = tid >> 2;          // 0..63
    const int aCol = (tid & 3) * 4;     // 0,4,8,12
    const int bRow = tid >> 5;          // 0..7
    const int bCol = (tid & 31) * 4;    // 0..124

    float acc[8][8];
#pragma unroll
    for (int i = 0; i < 8; i++)
#pragma unroll
        for (int j = 0; j < 8; j++) acc[i][j] = 0.f;

    for (int k0 = 0; k0 < K; k0 += 16) {
#pragma unroll
        for (int i = 0; i < 2; i++) {
            int r = aRow + i * 64;
            float4 v = *(const float4*)(Ab + (size_t)r * K + k0 + aCol);
            As[aCol + 0][r] = v.x;
            As[aCol + 1][r] = v.y;
            As[aCol + 2][r] = v.z;
            As[aCol + 3][r] = v.w;
        }
#pragma unroll
        for (int i = 0; i < 2; i++) {
            int r = bRow + i * 8;
            float4 v = *(const float4*)(Bb + (size_t)(k0 + r) * N + bCol);
            *(float4*)&Bs[r][bCol] = v;
        }
        __syncthreads();

#pragma unroll
        for (int kk = 0; kk < 16; kk++) {
            float ra[8], rb[8];
#pragma unroll
            for (int i = 0; i < 4; i++) {
                float4 v = *(const float4*)&As[kk][trow * 8 + 0];
                float4 w = *(const float4*)&As[kk][trow * 8 + 4];
                ra[0] = v.x; ra[1] = v.y; ra[2] = v.z; ra[3] = v.w;
                ra[4] = w.x; ra[5] = w.y; ra[6] = w.z; ra[7] = w.w;
                break;
            }
            {
                float4 v = *(const float4*)&Bs[kk][tcol * 8 + 0];
                float4 w = *(const float4*)&Bs[kk][tcol * 8 + 4];
                rb[0] = v.x; rb[1] = v.y; rb[2] = v.z; rb[3] = v.w;
                rb[4] = w.x; rb[5] = w.y; rb[6] = w.z; rb[7] = w.w;
            }
#pragma unroll
            for (int i = 0; i < 8; i++)
#pragma unroll
                for (int j = 0; j < 8; j++) acc[i][j] += ra[i] * rb[j];
        }
        __syncthreads();
    }

    float* Cb = C + (size_t)(by * 128) * N + bx * 128;
#pragma unroll
    for (int i = 0; i < 8; i++)
#pragma unroll
        for (int j = 0; j < 8; j += 4) {
            float4 v = make_float4(acc[i][j], acc[i][j + 1], acc[i][j + 2], acc[i][j + 3]);
            *(float4*)(Cb + (size_t)(trow * 8 + i) * N + tcol * 8 + j) = v;
        }
}

// ---------------- RoPE cos/sin table (fp64 for phase accuracy) -------------
__global__ void rope_table(const int* __restrict__ positions) {
    int idx = blockIdx.x * blockDim.x + threadIdx.x;  // t*64 + j
    if (idx >= 2048 * 64) return;
    int t = idx >> 6;
    int j = idx & 63;
    double inv = exp(-(double)j * (log(1.0e6) / 64.0));
    double f = (double)positions[t] * inv;
    g_cos[idx] = (float)cos(f);
    g_sin[idx] = (float)sin(f);
}

// ---------------- fused RMSNorm + RoPE (one warp per token-head) -----------
__global__ void rmsrope(float* __restrict__ X, int nheads, int rowstride,
                        const float* __restrict__ w) {
    int wid = (blockIdx.x * blockDim.x + threadIdx.x) >> 5;
    int lane = threadIdx.x & 31;
    int t = wid / nheads;
    int h = wid - t * nheads;
    if (t >= 2048) return;
    float* x = X + (size_t)t * rowstride + h * 128;

    float v0 = x[lane], v1 = x[lane + 32], v2 = x[lane + 64], v3 = x[lane + 96];
    float ss = v0 * v0 + v1 * v1 + v2 * v2 + v3 * v3;
#pragma unroll
    for (int off = 16; off > 0; off >>= 1) ss += __shfl_xor_sync(0xffffffffu, ss, off);
    float rms = rsqrtf(ss * (1.f / 128.f) + 1e-6f);

    v0 *= rms * w[lane];
    v1 *= rms * w[lane + 32];
    v2 *= rms * w[lane + 64];
    v3 *= rms * w[lane + 96];

    float c0 = g_cos[t * 64 + lane],      s0 = g_sin[t * 64 + lane];
    float c1 = g_cos[t * 64 + lane + 32], s1 = g_sin[t * 64 + lane + 32];

    x[lane]      = v0 * c0 - v2 * s0;
    x[lane + 64] = v2 * c0 + v0 * s0;
    x[lane + 32] = v1 * c1 - v3 * s1;
    x[lane + 96] = v3 * c1 + v1 * s1;
}

// ---------------- causal flash attention -----------------------------------
// grid (32 qblocks, 32 heads), 256 threads. BQ=BKV=64, D=128.
// smem: Qs[64][128], Kt[128][65] (transposed, pad), Vs[64][132], Ps[64][64]
#define ATTN_SMEM_FLOATS (64 * 128 + 128 * 65 + 64 * 132 + 64 * 64)
#define ATTN_SMEM_BYTES (ATTN_SMEM_FLOATS * 4)

__global__ __launch_bounds__(256) void attn_kernel(const float* __restrict__ Q,
                                                   const float* __restrict__ K,
                                                   const float* __restrict__ V,
                                                   float* __restrict__ O) {
    extern __shared__ float sm[];
    float* Qs = sm;                      // 64*128
    float* Kt = Qs + 64 * 128;           // 128*65
    float* Vs = Kt + 128 * 65;           // 64*132
    float* Ps = Vs + 64 * 132;           // 64*64

    const int qb = 31 - blockIdx.x;      // big tiles launch first
    const int h = blockIdx.y;
    const int kvh = h >> 2;              // group = NUM_Q/NUM_KV = 4
    const int tid = threadIdx.x;
    const int lane = tid & 31;
    const int w = tid >> 5;

    // load Q tile
    for (int idx = tid; idx < 64 * 128; idx += 256) {
        int r = idx >> 7, d = idx & 127;
        Qs[r * 128 + d] = Q[(size_t)(qb * 64 + r) * 4096 + h * 128 + d];
    }
    __syncthreads();

    float m[8], l[8], acc[8][4];
#pragma unroll
    for (int r = 0; r < 8; r++) {
        m[r] = -1e30f;
        l[r] = 0.f;
#pragma unroll
        for (int j = 0; j < 4; j++) acc[r][j] = 0.f;
    }

    const float scale = 0.08838834764831845f;  // 1/sqrt(128)

    for (int kb = 0; kb <= qb; kb++) {
        for (int idx = tid; idx < 64 * 128; idx += 256) {
            int r = idx >> 7, d = idx & 127;
            size_t g = (size_t)(kb * 64 + r) * 1024 + kvh * 128 + d;
            Kt[d * 65 + r] = K[g];
            Vs[r * 132 + d] = V[g];
        }
        __syncthreads();

#pragma unroll 1
        for (int r = 0; r < 8; r++) {
            const int rg = w * 8 + r;
            const int tq = qb * 64 + rg;
            const float* qrow = Qs + rg * 128;

            float s0 = 0.f, s1 = 0.f;
#pragma unroll 4
            for (int d = 0; d < 128; d++) {
                float qv = qrow[d];
                s0 += qv * Kt[d * 65 + lane];
                s1 += qv * Kt[d * 65 + lane + 32];
            }
            s0 *= scale;
            s1 *= scale;
            if (kb * 64 + lane > tq) s0 = -1e30f;
            if (kb * 64 + lane + 32 > tq) s1 = -1e30f;

            float mx = fmaxf(s0, s1);
#pragma unroll
            for (int off = 16; off > 0; off >>= 1)
                mx = fmaxf(mx, __shfl_xor_sync(0xffffffffu, mx, off));
            float mnew = fmaxf(m[r], mx);
            float p0 = __expf(s0 - mnew);
            float p1 = __expf(s1 - mnew);
            float ps = p0 + p1;
#pragma unroll
            for (int off = 16; off > 0; off >>= 1)
                ps += __shfl_xor_sync(0xffffffffu, ps, off);
            float corr = __expf(m[r] - mnew);
            l[r] = l[r] * corr + ps;
            m[r] = mnew;

            Ps[rg * 64 + lane] = p0;
            Ps[rg * 64 + lane + 32] = p1;
            __syncwarp();

            float4 a = make_float4(acc[r][0] * corr, acc[r][1] * corr,
                                   acc[r][2] * corr, acc[r][3] * corr);
#pragma unroll 4
            for (int k = 0; k < 64; k++) {
                float p = Ps[rg * 64 + k];
                float4 vv = *(const float4*)(Vs + k * 132 + lane * 4);
                a.x += p * vv.x;
                a.y += p * vv.y;
                a.z += p * vv.z;
                a.w += p * vv.w;
            }
            acc[r][0] = a.x; acc[r][1] = a.y; acc[r][2] = a.z; acc[r][3] = a.w;
            __syncwarp();
        }
        __syncthreads();
    }

#pragma unroll
    for (int r = 0; r < 8; r++) {
        int rg = w * 8 + r;
        int tq = qb * 64 + rg;
        float inv = 1.f / l[r];
        float4 o = make_float4(acc[r][0] * inv, acc[r][1] * inv,
                               acc[r][2] * inv, acc[r][3] * inv);
        *(float4*)(O + (size_t)tq * 4096 + h * 128 + lane * 4) = o;
    }
}

// ---------------- launch ----------------------------------------------------
extern "C" void kernel_launch(void* const* d_in, const int* in_sizes, int n_in,
                              void* d_out, int out_size) {
    const float* hidden    = (const float*)d_in[0];   // (2048, 4096)
    const int*   positions = (const int*)d_in[1];     // (2048,)
    const float* Wq        = (const float*)d_in[2];   // (4096, 4096)
    const float* Wk        = (const float*)d_in[3];   // (4096, 1024)
    const float* Wv        = (const float*)d_in[4];   // (4096, 1024)
    const float* Wo        = (const float*)d_in[5];   // (4096, 4096)
    const float* q_norm_w  = (const float*)d_in[6];   // (128,)
    const float* k_norm_w  = (const float*)d_in[7];   // (128,)
    float* out = (float*)d_out;

    float* q;    cudaGetSymbolAddress((void**)&q, g_q);
    float* k;    cudaGetSymbolAddress((void**)&k, g_k);
    float* v;    cudaGetSymbolAddress((void**)&v, g_v);
    float* attn; cudaGetSymbolAddress((void**)&attn, g_attn);

    // QKV projections
    sgemm128<<<dim3(32, 16), 256>>>(hidden, Wq, q, 2048, 4096, 4096);
    sgemm128<<<dim3(8, 16), 256>>>(hidden, Wk, k, 2048, 1024, 4096);
    sgemm128<<<dim3(8, 16), 256>>>(hidden, Wv, v, 2048, 1024, 4096);

    // RoPE table + fused rmsnorm/rope
    rope_table<<<(2048 * 64 + 255) / 256, 256>>>(positions);
    rmsrope<<<(2048 * 32) / 8, 256>>>(q, 32, 4096, q_norm_w);
    rmsrope<<<(2048 * 8) / 8, 256>>>(k, 8, 1024, k_norm_w);

    // attention
    cudaFuncSetAttribute(attn_kernel, cudaFuncAttributeMaxDynamicSharedMemorySize,
                         ATTN_SMEM_BYTES);
    attn_kernel<<<dim3(32, 32), 256, ATTN_SMEM_BYTES>>>(q, k, v, attn);

    // output projection
    sgemm128<<<dim3(32, 16), 256>>>(attn, Wo, out, 2048, 4096, 4096);
}